// round 13
// baseline (speedup 1.0000x reference)
#include <cuda_runtime.h>
#include <math.h>

// ----------------------------- problem constants ----------------------------
#define DDIM 256
#define LSEQ 1024
#define BATCH 2
#define CHK 16
#define NCH 64                     // chunks per sequence
#define NCHUNKS (BATCH * NCH)      // 128 total chunks
#define PPACK (4 * DDIM * DDIM)    // 262144 packed grad elems per chunk
#define EPSR 1.1920929e-07f

// ----------------------------- device scratch -------------------------------
__device__ float g_sn[BATCH * LSEQ * DDIM];     // store-norm rows
__device__ float g_rn[BATCH * LSEQ * DDIM];     // retrieve-norm rows, pre-shifted by C-1
__device__ float g_scal[NCHUNKS * 3];           // lr, mom, decay per chunk
__device__ float g_WT[3 * DDIM * DDIM];         // W1^T, W2^T, W3^T
__device__ float g_S[(size_t)NCHUNKS * PPACK];  // surprise = -lr * grads  (128 MB)
__device__ float g_U[(size_t)NCHUNKS * PPACK];  // cumulative updates      (128 MB)

// ----------------------------- helpers --------------------------------------
__device__ __forceinline__ float sigm(float z) { return 1.f / (1.f + __expf(-z)); }
__device__ __forceinline__ float siluprime(float z) {
    float s = sigm(z);
    return s * (1.f + z * (1.f - s));
}

// y[c][j] (thread j column) += x[16,256](smem) @ W[256,N] column j (ldw stride)
__device__ __forceinline__ void gemm16(const float* __restrict__ xs,
                                       const float* __restrict__ wcol, int ldw,
                                       float acc[CHK]) {
#pragma unroll 2
    for (int k = 0; k < DDIM; k += 4) {
        float w0 = wcol[(k + 0) * ldw];
        float w1 = wcol[(k + 1) * ldw];
        float w2 = wcol[(k + 2) * ldw];
        float w3 = wcol[(k + 3) * ldw];
#pragma unroll
        for (int c = 0; c < CHK; c++) {
            float4 xv = *reinterpret_cast<const float4*>(xs + c * DDIM + k);
            float a = acc[c];
            a = fmaf(xv.x, w0, a);
            a = fmaf(xv.y, w1, a);
            a = fmaf(xv.z, w2, a);
            a = fmaf(xv.w, w3, a);
            acc[c] = a;
        }
    }
}

// same, but weight column is W + U (fast weights)
__device__ __forceinline__ void gemm16_wu(const float* __restrict__ xs,
                                          const float* __restrict__ wcol,
                                          const float* __restrict__ ucol,
                                          float acc[CHK]) {
#pragma unroll 2
    for (int k = 0; k < DDIM; k += 4) {
        float w0 = wcol[(k + 0) * DDIM] + ucol[(k + 0) * DDIM];
        float w1 = wcol[(k + 1) * DDIM] + ucol[(k + 1) * DDIM];
        float w2 = wcol[(k + 2) * DDIM] + ucol[(k + 2) * DDIM];
        float w3 = wcol[(k + 3) * DDIM] + ucol[(k + 3) * DDIM];
#pragma unroll
        for (int c = 0; c < CHK; c++) {
            float4 xv = *reinterpret_cast<const float4*>(xs + c * DDIM + k);
            float a = acc[c];
            a = fmaf(xv.x, w0, a);
            a = fmaf(xv.y, w1, a);
            a = fmaf(xv.z, w2, a);
            a = fmaf(xv.w, w3, a);
            acc[c] = a;
        }
    }
}

// weight grad: Sout[p][j] = nlr * sum_c a[c][p] * d[c][j]   (thread j = column)
__device__ __forceinline__ void gemmB(const float* __restrict__ as,
                                      const float* __restrict__ ds,
                                      float* __restrict__ sout, float nlr, int j) {
    float dj[CHK];
#pragma unroll
    for (int c = 0; c < CHK; c++) dj[c] = ds[c * DDIM + j];
#pragma unroll 2
    for (int p = 0; p < DDIM; p += 4) {
        float a0 = 0.f, a1 = 0.f, a2 = 0.f, a3 = 0.f;
#pragma unroll
        for (int c = 0; c < CHK; c++) {
            float4 av = *reinterpret_cast<const float4*>(as + c * DDIM + p);
            a0 = fmaf(av.x, dj[c], a0);
            a1 = fmaf(av.y, dj[c], a1);
            a2 = fmaf(av.z, dj[c], a2);
            a3 = fmaf(av.w, dj[c], a3);
        }
        sout[(p + 0) * DDIM + j] = nlr * a0;
        sout[(p + 1) * DDIM + j] = nlr * a1;
        sout[(p + 2) * DDIM + j] = nlr * a2;
        sout[(p + 3) * DDIM + j] = nlr * a3;
    }
}

// ------------------ K1: rmsnorms (store + shifted retrieve) -----------------
__global__ __launch_bounds__(256) void k_norms(const float* __restrict__ seq,
                                               const float* __restrict__ w_store,
                                               const float* __restrict__ w_ret) {
    int gt = blockIdx.x;  // global token 0..2047
    int d = threadIdx.x;
    float x = seq[gt * DDIM + d];
    __shared__ float red[256];
    red[d] = x * x;
    __syncthreads();
    for (int s = 128; s > 0; s >>= 1) {
        if (d < s) red[d] += red[d + s];
        __syncthreads();
    }
    float r = rsqrtf(red[0] * (1.f / DDIM) + EPSR);
    g_sn[gt * DDIM + d] = x * r * w_store[d];
    float rv = x * r * w_ret[d];
    int b = gt >> 10, t = gt & (LSEQ - 1);
    // rn_padded[b, t-(C-1)] = rmsnorm(seq)[b, t]; tail rows are zero
    if (t >= CHK - 1)
        g_rn[(b * LSEQ + t - (CHK - 1)) * DDIM + d] = rv;
    else
        g_rn[(b * LSEQ + (LSEQ - (CHK - 1)) + t) * DDIM + d] = 0.f;
}

// ------------------ K2: per-chunk gate scalars -------------------------------
__global__ __launch_bounds__(256) void k_gates(const float* __restrict__ wa,
                                               const float* __restrict__ wm,
                                               const float* __restrict__ wd) {
    int ci = blockIdx.x;
    int d = threadIdx.x;
    const float* base = g_sn + ci * (CHK * DDIM) + d;
    float s = 0.f;
#pragma unroll
    for (int c = 0; c < CHK; c++) s += base[c * DDIM];
    float m = s * (1.f / CHK);
    float v[3] = {m * wa[d], m * wm[d], m * wd[d]};
    __shared__ float red[256];
    for (int i = 0; i < 3; i++) {
        red[d] = v[i];
        __syncthreads();
        for (int s2 = 128; s2 > 0; s2 >>= 1) {
            if (d < s2) red[d] += red[d + s2];
            __syncthreads();
        }
        if (d == 0) g_scal[ci * 3 + i] = 1.f / (1.f + __expf(-red[0]));
        __syncthreads();
    }
}

// ------------------ K3: transpose W1..W3 for backward ------------------------
__global__ __launch_bounds__(256) void k_transpose(const float* __restrict__ W1,
                                                   const float* __restrict__ W2,
                                                   const float* __restrict__ W3) {
    __shared__ float tile[32][33];
    int m = blockIdx.z;
    const float* W = (m == 0) ? W1 : (m == 1) ? W2 : W3;
    int bx = blockIdx.x * 32, by = blockIdx.y * 32;
    int x = threadIdx.x, y = threadIdx.y;  // 32 x 8
    for (int i = 0; i < 32; i += 8) tile[y + i][x] = W[(by + y + i) * DDIM + bx + x];
    __syncthreads();
    for (int i = 0; i < 32; i += 8)
        g_WT[m * DDIM * DDIM + (bx + y + i) * DDIM + by + x] = tile[x][y + i];
}

// ------------------ K4: per-chunk fwd + bwd grads → S ------------------------
__global__ __launch_bounds__(256) void k_grad(const float* __restrict__ Wkv,
                                              const float* __restrict__ W0,
                                              const float* __restrict__ W1,
                                              const float* __restrict__ W2,
                                              const float* __restrict__ W3) {
    extern __shared__ float sm[];
    float* Bk  = sm + 0 * 4096;  // keys (a0)
    float* Bv  = sm + 1 * 4096;  // vals -> dz3 -> dz1
    float* Bz0 = sm + 2 * 4096;
    float* Ba1 = sm + 3 * 4096;
    float* Bz1 = sm + 4 * 4096;
    float* Ba2 = sm + 5 * 4096;
    float* Bz2 = sm + 6 * 4096;
    float* Ba3 = sm + 7 * 4096;
    float* Bd  = sm + 8 * 4096;  // dz2 -> dz0
    float* Bsn = sm + 9 * 4096;

    int ci = blockIdx.x;
    int j = threadIdx.x;

    // load store-normed chunk rows [16,256]
    {
        const float4* src = reinterpret_cast<const float4*>(g_sn + (size_t)ci * CHK * DDIM);
        float4* dst = reinterpret_cast<float4*>(Bsn);
        for (int i = j; i < CHK * DDIM / 4; i += 256) dst[i] = src[i];
    }
    __syncthreads();

    float acc[CHK];
    // keys = sn @ Wkv[:, :D]
#pragma unroll
    for (int c = 0; c < CHK; c++) acc[c] = 0.f;
    gemm16(Bsn, Wkv + j, 2 * DDIM, acc);
#pragma unroll
    for (int c = 0; c < CHK; c++) Bk[c * DDIM + j] = acc[c];
    // vals = sn @ Wkv[:, D:]
#pragma unroll
    for (int c = 0; c < CHK; c++) acc[c] = 0.f;
    gemm16(Bsn, Wkv + DDIM + j, 2 * DDIM, acc);
#pragma unroll
    for (int c = 0; c < CHK; c++) Bv[c * DDIM + j] = acc[c];
    __syncthreads();

    // z0 = keys @ W0 ; a1 = silu(z0)
#pragma unroll
    for (int c = 0; c < CHK; c++) acc[c] = 0.f;
    gemm16(Bk, W0 + j, DDIM, acc);
#pragma unroll
    for (int c = 0; c < CHK; c++) {
        float z = acc[c];
        Bz0[c * DDIM + j] = z;
        Ba1[c * DDIM + j] = z * sigm(z);
    }
    __syncthreads();
    // z1 = a1 @ W1 ; a2 = silu(z1)
#pragma unroll
    for (int c = 0; c < CHK; c++) acc[c] = 0.f;
    gemm16(Ba1, W1 + j, DDIM, acc);
#pragma unroll
    for (int c = 0; c < CHK; c++) {
        float z = acc[c];
        Bz1[c * DDIM + j] = z;
        Ba2[c * DDIM + j] = z * sigm(z);
    }
    __syncthreads();
    // z2 = a2 @ W2 ; a3 = silu(z2)
#pragma unroll
    for (int c = 0; c < CHK; c++) acc[c] = 0.f;
    gemm16(Ba2, W2 + j, DDIM, acc);
#pragma unroll
    for (int c = 0; c < CHK; c++) {
        float z = acc[c];
        Bz2[c * DDIM + j] = z;
        Ba3[c * DDIM + j] = z * sigm(z);
    }
    __syncthreads();
    // pred = a3 @ W3 ; dz3 = 2*(pred - vals)/D  (in place into Bv)
#pragma unroll
    for (int c = 0; c < CHK; c++) acc[c] = 0.f;
    gemm16(Ba3, W3 + j, DDIM, acc);
#pragma unroll
    for (int c = 0; c < CHK; c++)
        Bv[c * DDIM + j] = (acc[c] - Bv[c * DDIM + j]) * (2.f / DDIM);
    __syncthreads();

    float nlr = -g_scal[ci * 3 + 0];
    float* Sc = g_S + (size_t)ci * PPACK;

    // gW3
    gemmB(Ba3, Bv, Sc + 3 * DDIM * DDIM, nlr, j);
    // dz2 = (dz3 @ W3^T) * silu'(z2)  -> Bd
#pragma unroll
    for (int c = 0; c < CHK; c++) acc[c] = 0.f;
    gemm16(Bv, g_WT + 2 * DDIM * DDIM + j, DDIM, acc);
#pragma unroll
    for (int c = 0; c < CHK; c++)
        Bd[c * DDIM + j] = acc[c] * siluprime(Bz2[c * DDIM + j]);
    __syncthreads();
    // gW2
    gemmB(Ba2, Bd, Sc + 2 * DDIM * DDIM, nlr, j);
    // dz1 = (dz2 @ W2^T) * silu'(z1) -> Bv
#pragma unroll
    for (int c = 0; c < CHK; c++) acc[c] = 0.f;
    gemm16(Bd, g_WT + 1 * DDIM * DDIM + j, DDIM, acc);
#pragma unroll
    for (int c = 0; c < CHK; c++)
        Bv[c * DDIM + j] = acc[c] * siluprime(Bz1[c * DDIM + j]);
    __syncthreads();
    // gW1
    gemmB(Ba1, Bv, Sc + 1 * DDIM * DDIM, nlr, j);
    // dz0 = (dz1 @ W1^T) * silu'(z0) -> Bd
#pragma unroll
    for (int c = 0; c < CHK; c++) acc[c] = 0.f;
    gemm16(Bv, g_WT + 0 * DDIM * DDIM + j, DDIM, acc);
#pragma unroll
    for (int c = 0; c < CHK; c++)
        Bd[c * DDIM + j] = acc[c] * siluprime(Bz0[c * DDIM + j]);
    __syncthreads();
    // gW0
    gemmB(Bk, Bd, Sc + 0 * DDIM * DDIM, nlr, j);
}

// ------------------ K5: double gated scan over chunks (per element) ----------
__global__ __launch_bounds__(256) void k_scan() {
    int b = blockIdx.y;
    size_t p = (size_t)blockIdx.x * 256 + threadIdx.x;
    __shared__ float sc[NCH * 2];
    if (threadIdx.x < NCH * 2) {
        int n = threadIdx.x >> 1;
        int w = threadIdx.x & 1;
        sc[threadIdx.x] = w ? (1.f - g_scal[(b * NCH + n) * 3 + 2])   // 1 - decay
                            : g_scal[(b * NCH + n) * 3 + 1];          // momentum gate
    }
    __syncthreads();
    const float* Sp = g_S + (size_t)b * NCH * PPACK + p;
    float* Up = g_U + (size_t)b * NCH * PPACK + p;
    float m = 0.f, u = 0.f;
#pragma unroll 8
    for (int n = 0; n < NCH; n++) {
        float s = Sp[(size_t)n * PPACK];
        m = fmaf(sc[2 * n], m, s);
        u = fmaf(sc[2 * n + 1], u, m);
        Up[(size_t)n * PPACK] = u;
    }
}

// ------------------ K6: retrieval MLP + postnorm + shift ---------------------
__global__ __launch_bounds__(256) void k_retrieve(const float* __restrict__ Wq,
                                                  const float* __restrict__ W0,
                                                  const float* __restrict__ W1,
                                                  const float* __restrict__ W2,
                                                  const float* __restrict__ W3,
                                                  const float* __restrict__ w_post,
                                                  float* __restrict__ out) {
    __shared__ __align__(16) float X[4096];
    __shared__ __align__(16) float Y[4096];
    __shared__ float rr[CHK];
    int ci = blockIdx.x;
    int j = threadIdx.x;
    int b = ci >> 6, n = ci & (NCH - 1);

    {
        const float4* src = reinterpret_cast<const float4*>(g_rn + (size_t)ci * CHK * DDIM);
        float4* dst = reinterpret_cast<float4*>(X);
        for (int i = j; i < CHK * DDIM / 4; i += 256) dst[i] = src[i];
    }
    __syncthreads();

    float acc[CHK];
    // q = rn @ Wq -> Y
#pragma unroll
    for (int c = 0; c < CHK; c++) acc[c] = 0.f;
    gemm16(X, Wq + j, DDIM, acc);
#pragma unroll
    for (int c = 0; c < CHK; c++) Y[c * DDIM + j] = acc[c];
    __syncthreads();

    const float* U = g_U + (size_t)ci * PPACK;
    // layer 0
#pragma unroll
    for (int c = 0; c < CHK; c++) acc[c] = 0.f;
    gemm16_wu(Y, W0 + j, U + 0 * DDIM * DDIM + j, acc);
#pragma unroll
    for (int c = 0; c < CHK; c++) { float z = acc[c]; X[c * DDIM + j] = z * sigm(z); }
    __syncthreads();
    // layer 1
#pragma unroll
    for (int c = 0; c < CHK; c++) acc[c] = 0.f;
    gemm16_wu(X, W1 + j, U + 1 * DDIM * DDIM + j, acc);
#pragma unroll
    for (int c = 0; c < CHK; c++) { float z = acc[c]; Y[c * DDIM + j] = z * sigm(z); }
    __syncthreads();
    // layer 2
#pragma unroll
    for (int c = 0; c < CHK; c++) acc[c] = 0.f;
    gemm16_wu(Y, W2 + j, U + 2 * DDIM * DDIM + j, acc);
#pragma unroll
    for (int c = 0; c < CHK; c++) { float z = acc[c]; X[c * DDIM + j] = z * sigm(z); }
    __syncthreads();
    // layer 3 (raw)
#pragma unroll
    for (int c = 0; c < CHK; c++) acc[c] = 0.f;
    gemm16_wu(X, W3 + j, U + 3 * DDIM * DDIM + j, acc);
#pragma unroll
    for (int c = 0; c < CHK; c++) Y[c * DDIM + j] = acc[c];
    __syncthreads();

    // post rmsnorm per row
    int warp = j >> 5, lane = j & 31;
    for (int c = warp; c < CHK; c += 8) {
        float s = 0.f;
        for (int i = lane; i < DDIM; i += 32) {
            float v = Y[c * DDIM + i];
            s = fmaf(v, v, s);
        }
        for (int o = 16; o; o >>= 1) s += __shfl_xor_sync(0xffffffffu, s, o);
        if (lane == 0) rr[c] = rsqrtf(s * (1.f / DDIM) + EPSR);
    }
    __syncthreads();

    // shift by C-1 and write
#pragma unroll
    for (int c = 0; c < CHK; c++) {
        int tdst = n * CHK + c + (CHK - 1);
        if (tdst < LSEQ)
            out[(b * LSEQ + tdst) * DDIM + j] = Y[c * DDIM + j] * rr[c] * w_post[j];
    }
    if (n == 0) {
#pragma unroll
        for (int c = 0; c < CHK - 1; c++) out[(b * LSEQ + c) * DDIM + j] = 0.f;
    }
}

// ----------------------------- launcher --------------------------------------
extern "C" void kernel_launch(void* const* d_in, const int* in_sizes, int n_in,
                              void* d_out, int out_size) {
    (void)in_sizes; (void)n_in; (void)out_size;
    const float* seq  = (const float*)d_in[0];
    const float* w_sn = (const float*)d_in[1];
    const float* w_rn = (const float*)d_in[2];
    const float* w_pn = (const float*)d_in[3];
    const float* Wq   = (const float*)d_in[4];
    const float* Wkv  = (const float*)d_in[5];
    const float* w_ad = (const float*)d_in[6];
    const float* w_mo = (const float*)d_in[7];
    const float* w_de = (const float*)d_in[8];
    const float* W0   = (const float*)d_in[9];
    const float* W1   = (const float*)d_in[10];
    const float* W2   = (const float*)d_in[11];
    const float* W3   = (const float*)d_in[12];
    float* out = (float*)d_out;

    const int grad_smem = 10 * 4096 * (int)sizeof(float);  // 160 KB
    cudaFuncSetAttribute(k_grad, cudaFuncAttributeMaxDynamicSharedMemorySize, grad_smem);

    k_norms<<<BATCH * LSEQ, 256>>>(seq, w_sn, w_rn);
    k_gates<<<NCHUNKS, 256>>>(w_ad, w_mo, w_de);
    k_transpose<<<dim3(8, 8, 3), dim3(32, 8)>>>(W1, W2, W3);
    k_grad<<<NCHUNKS, 256, grad_smem>>>(Wkv, W0, W1, W2, W3);
    k_scan<<<dim3(PPACK / 256, BATCH), 256>>>();
    k_retrieve<<<NCHUNKS, 256>>>(Wq, W0, W1, W2, W3, w_pn, out);
}